// round 5
// baseline (speedup 1.0000x reference)
#include <cuda_runtime.h>

#define BB 8
#define SS 2048
#define HH 1024
#define NT (BB * SS)     // 16384 tokens
#define PROD 128         // producer blocks (<=148: always resident in wave 1)
#define CONSPB 256       // consumer blocks per batch
#define RPB 8            // rows per consumer block

// Scratch (device globals — no allocation allowed in kernel_launch)
__device__ float g_ss[NT];      // score_s per token
__device__ float g_se[NT];      // score_e per token (+ bm folded in)
__device__ int   g_fl[NT];      // bit0 = start_cand, bit1 = end_cand
__device__ int   g_done[BB];    // per-batch producer-completion counters

__global__ void reset_kernel()
{
    if (threadIdx.x < BB) g_done[threadIdx.x] = 0;
}

// ---------------------------------------------------------------------------
// Fused pipeline. Producers (blocks 0..127): fold weights to smem, then for
// b = 0..7 compute 16 tokens of batch b (1 token per warp) and bump g_done[b].
// Consumers (blocks 128..2175): spin until their batch's scores are ready,
// then stream 8 rows of (valid, masked_scores) with __stcs. Writes of batch 0
// begin ~2us in, overlapping the remaining 56MB of reads.
// ---------------------------------------------------------------------------
__global__ void __launch_bounds__(512)
fused_kernel(const float* __restrict__ rep,
             const int*   __restrict__ mask,
             const float* __restrict__ Ws,  const float* __restrict__ bs,
             const float* __restrict__ We,  const float* __restrict__ be,
             const float* __restrict__ Wm,  const float* __restrict__ bm,
             float* __restrict__ out_valid,
             float* __restrict__ out_masked)
{
    const int tid = threadIdx.x;

    if (blockIdx.x < PROD) {
        // ------------------------------ producer ------------------------------
        __shared__ float s_wds[HH];   // Ws[:,1]-Ws[:,0]
        __shared__ float s_wss[HH];   // Wm0*Ws[:,0]+Wm1*Ws[:,1]
        __shared__ float s_wde[HH];   // We[:,1]-We[:,0]
        __shared__ float s_wse[HH];   // Wm2*We[:,0]+Wm3*We[:,1]
        __shared__ float s_bias[4];
        {
            const float wm0 = Wm[0], wm1 = Wm[1], wm2 = Wm[2], wm3 = Wm[3];
            #pragma unroll
            for (int p = 0; p < HH / 512; p++) {
                int h = p * 512 + tid;
                float a0 = Ws[2 * h], a1 = Ws[2 * h + 1];
                float c0 = We[2 * h], c1 = We[2 * h + 1];
                s_wds[h] = a1 - a0;
                s_wss[h] = wm0 * a0 + wm1 * a1;
                s_wde[h] = c1 - c0;
                s_wse[h] = wm2 * c0 + wm3 * c1;
            }
            if (tid == 0) {
                s_bias[0] = bs[1] - bs[0];
                s_bias[1] = wm0 * bs[0] + wm1 * bs[1];
                s_bias[2] = be[1] - be[0];
                s_bias[3] = wm2 * be[0] + wm3 * be[1] + bm[0];
            }
        }
        __syncthreads();

        const int warp = tid >> 5;
        const int lane = tid & 31;
        const float4* wds = reinterpret_cast<const float4*>(s_wds);
        const float4* wss = reinterpret_cast<const float4*>(s_wss);
        const float4* wde = reinterpret_cast<const float4*>(s_wde);
        const float4* wse = reinterpret_cast<const float4*>(s_wse);

        for (int b = 0; b < BB; b++) {
            const int t = b * SS + blockIdx.x * 16 + warp;   // one token per warp
            const float4* r4 = reinterpret_cast<const float4*>(rep + (size_t)t * HH);

            float ds = 0.f, sv = 0.f, de = 0.f, se = 0.f;
            #pragma unroll
            for (int k = 0; k < HH / 128; k++) {
                int idx = k * 32 + lane;
                float4 r = __ldcs(&r4[idx]);
                float4 a = wds[idx];
                float4 bw = wss[idx];
                float4 c = wde[idx];
                float4 d = wse[idx];
                ds += r.x*a.x  + r.y*a.y  + r.z*a.z  + r.w*a.w;
                sv += r.x*bw.x + r.y*bw.y + r.z*bw.z + r.w*bw.w;
                de += r.x*c.x  + r.y*c.y  + r.z*c.z  + r.w*c.w;
                se += r.x*d.x  + r.y*d.y  + r.z*d.z  + r.w*d.w;
            }
            #pragma unroll
            for (int off = 16; off; off >>= 1) {
                ds += __shfl_xor_sync(0xffffffffu, ds, off);
                sv += __shfl_xor_sync(0xffffffffu, sv, off);
                de += __shfl_xor_sync(0xffffffffu, de, off);
                se += __shfl_xor_sync(0xffffffffu, se, off);
            }
            if (lane == 0) {
                int m  = (mask[t] != 0);
                int sc = m && ((ds + s_bias[0]) >= 0.f);   // s0 <= s1
                int ec = m && ((de + s_bias[2]) >= 0.f);   // e0 <= e1
                g_ss[t] = sv + s_bias[1];
                g_se[t] = se + s_bias[3];
                g_fl[t] = sc | (ec << 1);
                __threadfence();        // each writer publishes its own stores
            }
            __syncthreads();            // all warps' fences done
            if (tid == 0) atomicAdd(&g_done[b], 1);
        }
    } else {
        // ------------------------------ consumer ------------------------------
        const int c  = blockIdx.x - PROD;
        const int b  = c / CONSPB;
        const int i0 = (c % CONSPB) * RPB;
        const int j4 = tid;
        const int j0 = j4 * 4;

        if (tid == 0) {
            while (*((volatile int*)&g_done[b]) < PROD) __nanosleep(64);
            __threadfence();
        }
        __syncthreads();

        // Per-column end scores/flags (L2-coherent with producer STGs)
        const float4 se4 = __ldcg(reinterpret_cast<const float4*>(g_se + b * SS) + j4);
        const int4   fl4 = __ldcg(reinterpret_cast<const int4*>(g_fl + b * SS) + j4);
        const bool e0 = fl4.x & 2, e1 = fl4.y & 2, e2 = fl4.z & 2, e3 = fl4.w & 2;

        #pragma unroll
        for (int r = 0; r < RPB; r++) {
            const int i = i0 + r;
            const int t = b * SS + i;
            const float ss = __ldcg(&g_ss[t]);
            const int   sc = __ldcg(&g_fl[t]) & 1;

            const size_t rowoff = ((size_t)b * SS + i) * SS;
            float4* ov = reinterpret_cast<float4*>(out_valid  + rowoff) + j4;
            float4* om = reinterpret_cast<float4*>(out_masked + rowoff) + j4;

            float4 v, m;
            if (!sc || (j0 + 3) < i) {
                v = make_float4(0.f, 0.f, 0.f, 0.f);
                m = v;
            } else {
                float ps; bool val;
                ps = ss + se4.x; val = e0 && (i <= j0 + 0) && (ps > 0.f);
                v.x = val ? 1.f : 0.f; m.x = val ? ps : 0.f;
                ps = ss + se4.y; val = e1 && (i <= j0 + 1) && (ps > 0.f);
                v.y = val ? 1.f : 0.f; m.y = val ? ps : 0.f;
                ps = ss + se4.z; val = e2 && (i <= j0 + 2) && (ps > 0.f);
                v.z = val ? 1.f : 0.f; m.z = val ? ps : 0.f;
                ps = ss + se4.w; val = e3 && (i <= j0 + 3) && (ps > 0.f);
                v.w = val ? 1.f : 0.f; m.w = val ? ps : 0.f;
            }
            __stcs(ov, v);
            __stcs(om, m);
        }
    }
}

extern "C" void kernel_launch(void* const* d_in, const int* in_sizes, int n_in,
                              void* d_out, int out_size)
{
    const float* rep  = (const float*)d_in[0];
    const int*   mask = (const int*)  d_in[1];
    const float* Ws   = (const float*)d_in[2];
    const float* bs   = (const float*)d_in[3];
    const float* We   = (const float*)d_in[4];
    const float* be   = (const float*)d_in[5];
    const float* Wm   = (const float*)d_in[6];
    const float* bm   = (const float*)d_in[7];

    float* out = (float*)d_out;
    const size_t half = (size_t)BB * SS * SS;   // valid first, masked second

    reset_kernel<<<1, 32>>>();
    fused_kernel<<<PROD + BB * CONSPB, 512>>>(rep, mask, Ws, bs, We, be, Wm, bm,
                                              out, out + half);
}

// round 6
// speedup vs baseline: 1.0421x; 1.0421x over previous
#include <cuda_runtime.h>

#define BB 8
#define SS 2048
#define HH 1024
#define NT (BB * SS)   // 16384 tokens

// Scratch (device globals — no allocation allowed in kernel_launch)
__device__ float g_ss[NT];      // score_s per token
__device__ float g_se[NT];      // score_e per token (+ bm folded in)
__device__ int   g_fl[NT];      // bit0 = start_cand, bit1 = end_cand

// ---------------------------------------------------------------------------
// Kernel 1: 256 threads = 8 warps; each warp 4 tokens -> 32 tokens/block,
// grid = 512 blocks (~3.5 resident waves of blocks/SM -> no tail cliff).
// Each smem weight float4 (LDS.128) feeds 4 rep rows: smem crossbar traffic
// drops 4x vs 1-token/warp; 4 independent LDG.128/iter give MLP>=8.
// DRAM-read bound: 64 MB.
// ---------------------------------------------------------------------------
__global__ void __launch_bounds__(256, 3)
logits_kernel(const float* __restrict__ rep,
              const int*   __restrict__ mask,
              const float* __restrict__ Ws,  const float* __restrict__ bs,
              const float* __restrict__ We,  const float* __restrict__ be,
              const float* __restrict__ Wm,  const float* __restrict__ bm)
{
    __shared__ float s_wds[HH];   // Ws[:,1]-Ws[:,0]
    __shared__ float s_wss[HH];   // Wm0*Ws[:,0]+Wm1*Ws[:,1]
    __shared__ float s_wde[HH];   // We[:,1]-We[:,0]
    __shared__ float s_wse[HH];   // Wm2*We[:,0]+Wm3*We[:,1]
    __shared__ float s_bias[4];

    const int tid = threadIdx.x;
    {
        const float wm0 = Wm[0], wm1 = Wm[1], wm2 = Wm[2], wm3 = Wm[3];
        #pragma unroll
        for (int p = 0; p < HH / 256; p++) {
            int h = p * 256 + tid;
            float a0 = Ws[2 * h], a1 = Ws[2 * h + 1];
            float c0 = We[2 * h], c1 = We[2 * h + 1];
            s_wds[h] = a1 - a0;
            s_wss[h] = wm0 * a0 + wm1 * a1;
            s_wde[h] = c1 - c0;
            s_wse[h] = wm2 * c0 + wm3 * c1;
        }
        if (tid == 0) {
            s_bias[0] = bs[1] - bs[0];
            s_bias[1] = wm0 * bs[0] + wm1 * bs[1];
            s_bias[2] = be[1] - be[0];
            s_bias[3] = wm2 * be[0] + wm3 * be[1] + bm[0];
        }
    }
    __syncthreads();

    const int warp = tid >> 5;
    const int lane = tid & 31;
    const int t0   = blockIdx.x * 32 + warp * 4;   // first of 4 tokens

    const float4* r40 = reinterpret_cast<const float4*>(rep + (size_t)(t0 + 0) * HH);
    const float4* r41 = reinterpret_cast<const float4*>(rep + (size_t)(t0 + 1) * HH);
    const float4* r42 = reinterpret_cast<const float4*>(rep + (size_t)(t0 + 2) * HH);
    const float4* r43 = reinterpret_cast<const float4*>(rep + (size_t)(t0 + 3) * HH);

    const float4* wds = reinterpret_cast<const float4*>(s_wds);
    const float4* wss = reinterpret_cast<const float4*>(s_wss);
    const float4* wde = reinterpret_cast<const float4*>(s_wde);
    const float4* wse = reinterpret_cast<const float4*>(s_wse);

    float ds[4] = {0,0,0,0}, sv[4] = {0,0,0,0}, de[4] = {0,0,0,0}, se[4] = {0,0,0,0};

    #pragma unroll 2
    for (int k = 0; k < HH / 128; k++) {
        int idx = k * 32 + lane;
        float4 r0 = __ldcs(&r40[idx]);
        float4 r1 = __ldcs(&r41[idx]);
        float4 r2 = __ldcs(&r42[idx]);
        float4 r3 = __ldcs(&r43[idx]);
        float4 a = wds[idx];
        float4 b = wss[idx];
        float4 c = wde[idx];
        float4 d = wse[idx];

        ds[0] += r0.x*a.x + r0.y*a.y + r0.z*a.z + r0.w*a.w;
        sv[0] += r0.x*b.x + r0.y*b.y + r0.z*b.z + r0.w*b.w;
        de[0] += r0.x*c.x + r0.y*c.y + r0.z*c.z + r0.w*c.w;
        se[0] += r0.x*d.x + r0.y*d.y + r0.z*d.z + r0.w*d.w;

        ds[1] += r1.x*a.x + r1.y*a.y + r1.z*a.z + r1.w*a.w;
        sv[1] += r1.x*b.x + r1.y*b.y + r1.z*b.z + r1.w*b.w;
        de[1] += r1.x*c.x + r1.y*c.y + r1.z*c.z + r1.w*c.w;
        se[1] += r1.x*d.x + r1.y*d.y + r1.z*d.z + r1.w*d.w;

        ds[2] += r2.x*a.x + r2.y*a.y + r2.z*a.z + r2.w*a.w;
        sv[2] += r2.x*b.x + r2.y*b.y + r2.z*b.z + r2.w*b.w;
        de[2] += r2.x*c.x + r2.y*c.y + r2.z*c.z + r2.w*c.w;
        se[2] += r2.x*d.x + r2.y*d.y + r2.z*d.z + r2.w*d.w;

        ds[3] += r3.x*a.x + r3.y*a.y + r3.z*a.z + r3.w*a.w;
        sv[3] += r3.x*b.x + r3.y*b.y + r3.z*b.z + r3.w*b.w;
        de[3] += r3.x*c.x + r3.y*c.y + r3.z*c.z + r3.w*c.w;
        se[3] += r3.x*d.x + r3.y*d.y + r3.z*d.z + r3.w*d.w;
    }

    #pragma unroll
    for (int tt = 0; tt < 4; tt++) {
        float x0 = ds[tt], x1 = sv[tt], x2 = de[tt], x3 = se[tt];
        #pragma unroll
        for (int off = 16; off; off >>= 1) {
            x0 += __shfl_xor_sync(0xffffffffu, x0, off);
            x1 += __shfl_xor_sync(0xffffffffu, x1, off);
            x2 += __shfl_xor_sync(0xffffffffu, x2, off);
            x3 += __shfl_xor_sync(0xffffffffu, x3, off);
        }
        if (lane == 0) {
            int t  = t0 + tt;
            int m  = (mask[t] != 0);
            int sc = m && ((x0 + s_bias[0]) >= 0.f);   // s0 <= s1
            int ec = m && ((x2 + s_bias[2]) >= 0.f);   // e0 <= e1
            g_ss[t] = x1 + s_bias[1];
            g_se[t] = x3 + s_bias[3];
            g_fl[t] = sc | (ec << 1);
        }
    }
}

// ---------------------------------------------------------------------------
// Kernel 2: one block per (b, i) row; 512 threads x float4 covers S=2048 cols.
// Pure HBM-write bound (268 MB) — measured at the store-path floor (~5.2TB/s
// DRAM) across 3 structural variants; keep the simplest/cheapest form.
// ---------------------------------------------------------------------------
__global__ void __launch_bounds__(512)
pair_kernel(float* __restrict__ out_valid,
            float* __restrict__ out_masked)
{
    const int i = blockIdx.x;
    const int b = blockIdx.y;
    const int t = b * SS + i;

    const float ss = g_ss[t];
    const bool  sc = (g_fl[t] & 1);

    const size_t rowoff = ((size_t)b * SS + i) * SS;
    float4* ov = reinterpret_cast<float4*>(out_valid  + rowoff);
    float4* om = reinterpret_cast<float4*>(out_masked + rowoff);

    const int j4 = threadIdx.x;        // one float4 (4 j's) per thread
    const int j0 = j4 * 4;

    float4 v, m;
    if (!sc || (j0 + 3) < i) {
        v = make_float4(0.f, 0.f, 0.f, 0.f);
        m = v;
    } else {
        const float4 se4 = reinterpret_cast<const float4*>(g_se + b * SS)[j4];
        const int4   fl4 = reinterpret_cast<const int4*>(g_fl + b * SS)[j4];

        float ps; bool val;
        ps = ss + se4.x; val = (fl4.x & 2) && (i <= j0 + 0) && (ps > 0.f);
        v.x = val ? 1.f : 0.f; m.x = val ? ps : 0.f;
        ps = ss + se4.y; val = (fl4.y & 2) && (i <= j0 + 1) && (ps > 0.f);
        v.y = val ? 1.f : 0.f; m.y = val ? ps : 0.f;
        ps = ss + se4.z; val = (fl4.z & 2) && (i <= j0 + 2) && (ps > 0.f);
        v.z = val ? 1.f : 0.f; m.z = val ? ps : 0.f;
        ps = ss + se4.w; val = (fl4.w & 2) && (i <= j0 + 3) && (ps > 0.f);
        v.w = val ? 1.f : 0.f; m.w = val ? ps : 0.f;
    }
    __stcs(ov + j4, v);
    __stcs(om + j4, m);
}

extern "C" void kernel_launch(void* const* d_in, const int* in_sizes, int n_in,
                              void* d_out, int out_size)
{
    const float* rep  = (const float*)d_in[0];
    const int*   mask = (const int*)  d_in[1];
    const float* Ws   = (const float*)d_in[2];
    const float* bs   = (const float*)d_in[3];
    const float* We   = (const float*)d_in[4];
    const float* be   = (const float*)d_in[5];
    const float* Wm   = (const float*)d_in[6];
    const float* bm   = (const float*)d_in[7];

    float* out = (float*)d_out;
    const size_t half = (size_t)BB * SS * SS;   // valid first, masked second

    logits_kernel<<<NT / 32, 256>>>(rep, mask, Ws, bs, We, be, Wm, bm);

    dim3 g2(SS, BB);
    pair_kernel<<<g2, 512>>>(out, out + half);
}